// round 17
// baseline (speedup 1.0000x reference)
#include <cuda_runtime.h>
#include <cstdint>
#include <math.h>

// ---------------------------------------------------------------------------
// ClassicalMappedQRNN fast path (alpha=beta=pi/2). B=8192 chains, S=4096.
// R17: MONOLITHIC scalar fused double-step. 128 blocks x 64 thr: 256 warps,
// each on a PRIVATE SMSP (2 warps/block -> SMSP 0,1 of each SM).
// Rationale from R14/R16: specialized consumer+producer configs are capped at
// >=129us by fma-pipe capacity per consumer SMSP (2 warps share one pipe) or
// by solo-warp stalls. Monolithic floor = 22.5 fma/step x rt2 = 45 cyc/step
// = 93us, and inline trig-lookahead gives the scheduler independent filler
// (R6 proved near-saturated issue in monolithic form). Scalar math avoids
// R6's f32x2 pack/unpack bloat: ~39 fma + 6 MUFU per 2-step pair.
// Math (proven in R14/R16, rel_err 8.8e-6):
//   C = sqrt2*cos(phi/2) = sqrt(1+r), S = sqrt2*sin(phi/2) = x r/sqrt(1+r),
//   r = rsqrt(1+x^2);  v = (C,-S,S,C), ||v|| = 2;  K = sqrt2/||G||
//   pair (R^2 = 2J, J(g)=(-g1,g0,g3,-g2)):
//     cc = C C2 + S S2; P = C+S; M = C-S
//     a = g0-g1-g2+g3; b = g2+g3-g0-g1; d1 = C a + S b
//     m1 = 4 + K1 d1;  K2 = rsqrt(m1)
//     e = C2(g1+g2) + S2(g0-g3);  hf = cc - K1 e
//     m2 = 4 + 2K2 hf; K3 = rsqrt(m2)
//     G' = 2K2K1 J(G) + K2 (P,M,P,M) + (C2,-S2,S2,C2)
// Input: register double-buffered chunks of 16 (4x LDG.128), no smem/barriers.
// Exact renorm every 16 steps kills approx-rsqrt drift.
// ---------------------------------------------------------------------------

#define CHUNK  16
#define TPB    64
#define GUARD4 4.000021f

__device__ __forceinline__ float rsqa(float x) {
    float y; asm("rsqrt.approx.f32 %0, %1;" : "=f"(y) : "f"(x)); return y;
}

// ---------------- trig ----------------
struct TrigP { float C0, S0, C1, S1; };

__device__ __forceinline__ float trig1(float x, float& S) {
    float tq = fmaf(x, x, 1.0f);
    float r  = rsqa(tq);
    float e  = r + 1.0f;
    float q  = rsqa(e);
    S = (x * r) * q;                       // sqrt2 sin(phi/2)
    return e * q;                          // sqrt2 cos(phi/2)
}
__device__ __forceinline__ TrigP trigp(float x0, float x1) {
    TrigP t;
    t.C0 = trig1(x0, t.S0);
    t.C1 = trig1(x1, t.S1);
    return t;
}

// ---------------- state ----------------
struct SState { float g0, g1, g2, g3, K; };

__device__ __forceinline__ void s_init(SState& s, float C, float S) {
    s.g0 = C; s.g1 = -S; s.g2 = S; s.g3 = C;           // G0 = v0
    s.K  = 0.70710678118654752f;                        // sqrt2/||G0||
}

__device__ __forceinline__ void s_direct(SState& s, float C, float S) {
    float w0 = s.g0 - s.g1, w1 = s.g0 + s.g1;
    float w2 = s.g2 + s.g3, w3 = s.g3 - s.g2;
    float d  = fmaf(S, w2 - w1, C * (w0 + w3));
    float m  = fmaf(s.K, d, GUARD4);
    float Kn = rsqa(m);
    float n0 = fmaf(s.K, w0,  C);
    float n1 = fmaf(s.K, w1, -S);
    float n2 = fmaf(s.K, w2,  S);
    float n3 = fmaf(s.K, w3,  C);
    s.g0 = n0; s.g1 = n1; s.g2 = n2; s.g3 = n3; s.K = Kn;
}

__device__ __forceinline__ void s_pair(SState& s, TrigP q) {
    float C = q.C0, Sx = q.S0, C2 = q.C1, S2 = q.S1;
    float cc = fmaf(Sx, S2, C * C2);
    float P  = C + Sx;
    float M  = C - Sx;
    float w01 = s.g0 - s.g1, w23 = s.g2 - s.g3;
    float p01 = s.g0 + s.g1, p23 = s.g2 + s.g3;
    float a = w01 - w23;
    float b = p23 - p01;
    float d1 = fmaf(Sx, b, C * a);
    float m1 = fmaf(s.K, d1, GUARD4);
    float K2 = rsqa(m1);                              // chain
    float gam = s.g1 + s.g2;
    float bet = s.g0 - s.g3;
    float e   = fmaf(S2, bet, C2 * gam);
    float hf  = fmaf(-s.K, e, cc);
    float K22 = K2 + K2;
    float m2  = fmaf(K22, hf, GUARD4);
    float K3  = rsqa(m2);                             // chain
    float KK2 = K22 * s.K;                            // 2 K2 K1
    float KP  = K2 * P;
    float KM  = K2 * M;
    float n0 = fmaf(-KK2, s.g1, KP + C2);
    float n2 = fmaf( KK2, s.g3, KP + S2);
    float n1 = fmaf( KK2, s.g0, KM - S2);
    float n3 = fmaf(-KK2, s.g2, KM + C2);
    s.g0 = n0; s.g1 = n1; s.g2 = n2; s.g3 = n3; s.K = K3;
}

__device__ __forceinline__ void s_renorm(SState& s) {
    float ss = (s.g0 * s.g0 + s.g1 * s.g1) + (s.g2 * s.g2 + s.g3 * s.g3);
    s.K = rsqa(0.5f * ss);                            // exact sqrt2/||G||
}

// ---------------- input chunks ----------------
struct PReg { float4 a[4]; };   // 16 x's = 8 pairs

__device__ __forceinline__ void p_load(PReg& r, const float* __restrict__ xrow,
                                       int c) {
    const float4* p = reinterpret_cast<const float4*>(xrow + c * CHUNK);
    #pragma unroll
    for (int i = 0; i < 4; i++) r.a[i] = __ldg(p + i);
}

// One chunk: 8 pairs, trig computed ONE PAIR AHEAD (independent filler work).
// tg enters holding pair-0 trig of this chunk; exits holding pair-0 trig of
// the NEXT chunk (from nx0, nx1 = that chunk's first two x's).
template <bool FIRST>
__device__ __forceinline__ void proc_chunk(SState& s, TrigP& tg,
                                           const PReg& cur,
                                           float nx0, float nx1) {
    float xs[16];
    #pragma unroll
    for (int i = 0; i < 4; i++) {
        xs[4 * i + 0] = cur.a[i].x; xs[4 * i + 1] = cur.a[i].y;
        xs[4 * i + 2] = cur.a[i].z; xs[4 * i + 3] = cur.a[i].w;
    }
    if (FIRST) {
        TrigP t0 = trigp(xs[0], xs[1]);
        s_init(s, t0.C0, t0.S0);                    // step 0: G = v0
        s_direct(s, t0.C1, t0.S1);                  // step 1: direct
        tg = trigp(xs[2], xs[3]);                   // pair 1
        #pragma unroll
        for (int p = 1; p < 8; p++) {
            TrigP nt = (p < 7) ? trigp(xs[2 * p + 2], xs[2 * p + 3])
                               : trigp(nx0, nx1);
            s_pair(s, tg);
            tg = nt;
        }
    } else {
        #pragma unroll
        for (int p = 0; p < 8; p++) {
            TrigP nt = (p < 7) ? trigp(xs[2 * p + 2], xs[2 * p + 3])
                               : trigp(nx0, nx1);
            s_pair(s, tg);
            tg = nt;
        }
    }
    s_renorm(s);   // exact rescale every 16 steps
}

__device__ void run_fast(const float* __restrict__ xrow,
                         float* __restrict__ outb, int S) {
    const int nch = S / CHUNK;                 // even (S % 32 == 0), >= 2
    SState s;
    TrigP tg;
    PReg A, Bb;

    p_load(A, xrow, 0);
    p_load(Bb, xrow, 1);
    proc_chunk<true>(s, tg, A, Bb.a[0].x, Bb.a[0].y);     // chunk 0

    #pragma unroll 1
    for (int c = 1; c < nch; c += 2) {
        if (c + 1 < nch) p_load(A, xrow, c + 1);           // chunk c+1 -> A
        proc_chunk<false>(s, tg, Bb, A.a[0].x, A.a[0].y);  // chunk c
        if (c + 1 < nch) {
            if (c + 2 < nch) p_load(Bb, xrow, c + 2);      // chunk c+2 -> B
            proc_chunk<false>(s, tg, A, Bb.a[0].x, Bb.a[0].y); // chunk c+1
        }
    }

    float a01 = s.g0 * s.g0 + s.g1 * s.g1;
    float a23 = s.g2 * s.g2 + s.g3 * s.g3;
    *outb = (a01 - a23) / (a01 + a23);
}

// ---------------- fallback ----------------
__device__ void run_simple(const float* __restrict__ xrow, float* __restrict__ outb,
                           int S, float ca, float sa, float cb, float sb) {
    float h0 = 0.f, h1 = 0.f, h2 = 0.f, h3 = 0.f;
    for (int t = 0; t < S; t++) {
        float xv = xrow[t];
        float phi = atanf(xv);
        float c = cosf(0.5f * phi);
        float s = sinf(0.5f * phi);
        float u0 = ca * c + cb * h0 - sb * h1;
        float u1 = -(sa * s) + sb * h0 + cb * h1;
        float u2 = ca * s + cb * h2 + sb * h3;
        float u3 = sa * c - sb * h2 + cb * h3;
        float ss = u0*u0 + u1*u1 + u2*u2 + u3*u3;
        float rn = rsqrtf(ss);
        h0 = u0 * rn; h1 = u1 * rn; h2 = u2 * rn; h3 = u3 * rn;
    }
    *outb = (h0*h0 + h1*h1) - (h2*h2 + h3*h3);
}

// ---------------- kernel ----------------
__global__ void __launch_bounds__(TPB, 1)
qrnn_kernel(const float* __restrict__ x, const float* __restrict__ pa,
            const float* __restrict__ pb, float* __restrict__ out, int B, int S) {
    int tid = threadIdx.x;
    int b   = blockIdx.x * TPB + tid;
    if (b >= B) return;

    float alpha = __ldg(pa);
    float beta  = __ldg(pb);
    const float PIO2 = 1.57079632679489662f;
    bool fast = (fabsf(alpha - PIO2) < 1e-5f) && (fabsf(beta - PIO2) < 1e-5f)
                && (S % 32 == 0) && (S >= 64);

    const float* xrow = x + (size_t)b * (size_t)S;
    float* outb = out + b;

    if (fast) {
        run_fast(xrow, outb, S);
    } else {
        float ca = cosf(0.5f * alpha), sa = sinf(0.5f * alpha);
        float cb = cosf(0.5f * beta),  sb = sinf(0.5f * beta);
        run_simple(xrow, outb, S, ca, sa, cb, sb);
    }
}

extern "C" void kernel_launch(void* const* d_in, const int* in_sizes, int n_in,
                              void* d_out, int out_size) {
    const float* x  = (const float*)d_in[0];
    const float* pa = (const float*)d_in[1];
    const float* pb = (const float*)d_in[2];
    float* out = (float*)d_out;

    int B = out_size;                 // 8192
    int S = in_sizes[0] / B;          // 4096

    int grid = (B + TPB - 1) / TPB;   // 128 blocks x 64 threads:
    qrnn_kernel<<<grid, TPB>>>(x, pa, pb, out, B, S);   // 1 warp per SMSP
}